// round 14
// baseline (speedup 1.0000x reference)
#include <cuda_runtime.h>
#include <cuda_bf16.h>
#include <cuda_fp16.h>
#include <mma.h>
#include <math_constants.h>

using namespace nvcuda;

// Problem constants
#define BB 2
#define S  2048
#define DD 1024
#define H  16
#define HD 64
#define BH (BB*H)       // 32
#define MROWS (BB*S)    // 4096
#define MASK_N (BB*S*S) // 8,388,608

// Scratch (device globals: allocation-free)
__device__ __half g_q16[BH * S * HD];          // Q (scale folded), fp16
__device__ __half g_k16[BH * S * HD];          // K, fp16
__device__ __half g_v16[BH * S * HD];          // V, fp16
__device__ __half g_e16[(size_t)BH * S * S];   // exp(scores), fp16 (268MB)
__device__ float g_rowsum[BH * S];
__device__ unsigned char g_mask_u8[MASK_N];
__device__ int g_mask_mode;
__device__ float g_attn_scratch[(size_t)BH * S * S]; // fallback if d_out only holds ctx

// ---------------------------------------------------------------------------
// exp2 via magic-constant round + deg-4 Taylor (feeds fp16 storage).
// ---------------------------------------------------------------------------
__device__ __forceinline__ float fast_exp2(float y) {
    y = fminf(fmaxf(y, -24.0f), 15.5f);
    float z = y + 12582912.0f;                 // 0x1.8p23: round(y) in low bits
    float r = z - 12582912.0f;                 // exact round(y)
    float f = y - r;                           // exact, in [-0.5, 0.5]
    float sc = __int_as_float((__float_as_int(z) + 127) << 23);  // 2^r
    float p = 9.6181291e-3f;                   // ln2^4/24
    p = fmaf(p, f, 5.5504109e-2f);             // ln2^3/6
    p = fmaf(p, f, 2.4022651e-1f);             // ln2^2/2
    p = fmaf(p, f, 6.9314718e-1f);             // ln2
    p = fmaf(p, f, 1.0f);
    return p * sc;
}

__device__ __forceinline__ void split_bf(float x, __nv_bfloat16& h, __nv_bfloat16& l) {
    h = __float2bfloat16(x);
    l = __float2bfloat16(x - __bfloat162float(h));
}
__device__ __forceinline__ unsigned cvt2h(float a, float b) {
    __half2 t = __float22half2_rn(make_float2(a, b));
    return *(unsigned*)&t;
}
// fp32 warp reduce: redux.f32 does NOT exist on sm_103 — shfl tree.
__device__ __forceinline__ float warp_sum(float v) {
#pragma unroll
    for (int o = 16; o > 0; o >>= 1) v += __shfl_xor_sync(0xffffffffu, v, o);
    return v;
}

// ---------------------------------------------------------------------------
// Mask dtype detection + conversion (proven R2-R13)
// ---------------------------------------------------------------------------
__global__ void detect_mask_kernel(const unsigned int* __restrict__ w) {
    __shared__ int s_int, s_float;
    if (threadIdx.x == 0) { s_int = 1; s_float = 1; }
    __syncthreads();
    int li = 1, lf = 1;
    for (int i = threadIdx.x; i < 2048; i += 256) {
        unsigned int x = w[i];
        if (x != 0u && x != 1u) li = 0;
        if (x != 0u && x != 0x3f800000u) lf = 0;
    }
    if (!li) atomicAnd(&s_int, 0);
    if (!lf) atomicAnd(&s_float, 0);
    __syncthreads();
    if (threadIdx.x == 0) g_mask_mode = s_int ? 1 : (s_float ? 2 : 0);
}

__global__ void convert_mask_kernel(const void* __restrict__ mraw,
                                    unsigned char* __restrict__ mu8) {
    int i = blockIdx.x * blockDim.x + threadIdx.x;
    if (i >= MASK_N) return;
    int mode = g_mask_mode;
    unsigned char v;
    if (mode == 0)      v = ((const unsigned char*)mraw)[i];
    else if (mode == 1) v = (unsigned char)(((const int*)mraw)[i] != 0);
    else                v = (unsigned char)(((const float*)mraw)[i] != 0.0f);
    mu8[i] = v;
}

// ---------------------------------------------------------------------------
// Projection (all 3 via z): C = X*W^T + bias, *scale. GEMM in bf16 hi/lo;
// outputs single fp16 head-split. Q (z=0) folds 0.125*log2(e).
// ---------------------------------------------------------------------------
__global__ void __launch_bounds__(256, 2)
proj_wmma(const float* __restrict__ X0, const float* __restrict__ X1, const float* __restrict__ X2,
          const float* __restrict__ W0, const float* __restrict__ W1, const float* __restrict__ W2,
          const float* __restrict__ B0, const float* __restrict__ B1, const float* __restrict__ B2,
          __half* __restrict__ O0, __half* __restrict__ O1, __half* __restrict__ O2) {
    extern __shared__ char smraw[];
    __nv_bfloat16* sAh = (__nv_bfloat16*)smraw;        // [128][40]
    __nv_bfloat16* sAl = sAh + 128 * 40;
    __nv_bfloat16* sBh = sAl + 128 * 40;
    __nv_bfloat16* sBl = sBh + 128 * 40;
    float* sC = (float*)smraw;                         // [128][136] (aliased)

    const float *X, *W, *Bv; __half* O; float scale;
    const int mode = blockIdx.z;
    if (mode == 0)      { X = X0; W = W0; Bv = B0; O = O0;
                          scale = 0.18033688011111378f; }   // 0.125*log2(e)
    else if (mode == 1) { X = X1; W = W1; Bv = B1; O = O1; scale = 1.0f; }
    else                { X = X2; W = W2; Bv = B2; O = O2; scale = 1.0f; }

    const int tid = threadIdx.x;
    const int warp = tid >> 5, wm = warp >> 1, wn = warp & 1;
    const int m0 = blockIdx.y * 128, n0 = blockIdx.x * 128;
    const int lr = tid >> 3, lc = tid & 7;

    wmma::fragment<wmma::accumulator, 16, 16, 16, float> acc[2][4];
#pragma unroll
    for (int i = 0; i < 2; i++)
#pragma unroll
        for (int j = 0; j < 4; j++) wmma::fill_fragment(acc[i][j], 0.0f);

    for (int k0 = 0; k0 < DD; k0 += 32) {
#pragma unroll
        for (int it = 0; it < 4; it++) {
            int r = lr + it * 32;
            float4 xv = *(const float4*)(X + (size_t)(m0 + r) * DD + k0 + lc * 4);
            float4 wv = *(const float4*)(W + (size_t)(n0 + r) * DD + k0 + lc * 4);
            int sa = r * 40 + lc * 4;
            float xs[4] = {xv.x, xv.y, xv.z, xv.w};
            float ws[4] = {wv.x, wv.y, wv.z, wv.w};
#pragma unroll
            for (int j = 0; j < 4; j++) {
                __nv_bfloat16 h, l;
                split_bf(xs[j], h, l); sAh[sa + j] = h; sAl[sa + j] = l;
                split_bf(ws[j], h, l); sBh[sa + j] = h; sBl[sa + j] = l;
            }
        }
        __syncthreads();
#pragma unroll
        for (int kk = 0; kk < 32; kk += 16) {
            wmma::fragment<wmma::matrix_a, 16, 16, 16, __nv_bfloat16, wmma::row_major> ah[2], al[2];
#pragma unroll
            for (int i = 0; i < 2; i++) {
                wmma::load_matrix_sync(ah[i], sAh + (wm * 32 + i * 16) * 40 + kk, 40);
                wmma::load_matrix_sync(al[i], sAl + (wm * 32 + i * 16) * 40 + kk, 40);
            }
#pragma unroll
            for (int j = 0; j < 4; j++) {
                wmma::fragment<wmma::matrix_b, 16, 16, 16, __nv_bfloat16, wmma::col_major> bh_, bl_;
                wmma::load_matrix_sync(bh_, sBh + (wn * 64 + j * 16) * 40 + kk, 40);
                wmma::load_matrix_sync(bl_, sBl + (wn * 64 + j * 16) * 40 + kk, 40);
#pragma unroll
                for (int i = 0; i < 2; i++) {
                    wmma::mma_sync(acc[i][j], ah[i], bh_, acc[i][j]);
                    wmma::mma_sync(acc[i][j], ah[i], bl_, acc[i][j]);
                    wmma::mma_sync(acc[i][j], al[i], bh_, acc[i][j]);
                }
            }
        }
        __syncthreads();
    }

#pragma unroll
    for (int i = 0; i < 2; i++)
#pragma unroll
        for (int j = 0; j < 4; j++)
            wmma::store_matrix_sync(sC + (wm * 32 + i * 16) * 136 + wn * 64 + j * 16,
                                    acc[i][j], 136, wmma::mem_row_major);
    __syncthreads();

#pragma unroll
    for (int it = 0; it < 16; it++) {
        int idx = tid + it * 256;
        int r = idx >> 5, c4 = (idx & 31) * 4;
        float4 v = *(float4*)&sC[r * 136 + c4];
        float4 bb = *(const float4*)&Bv[n0 + c4];
        int gc = n0 + c4;
        int hh = gc >> 6, d = gc & 63;
        int gr = m0 + r;
        int b = gr >> 11, s = gr & (S - 1);
        size_t p = (((size_t)(b * H + hh)) * S + s) * HD + d;
        uint2 u;
        u.x = cvt2h((v.x + bb.x) * scale, (v.y + bb.y) * scale);
        u.y = cvt2h((v.z + bb.z) * scale, (v.w + bb.w) * scale);
        *(uint2*)&O[p] = u;
    }
}

// ---------------------------------------------------------------------------
// Scores (R12-proven, 234us): 128q x 128k tile, d=64 resident, single fp16
// MMA per k-step. Block epilogue with sC round-trip.
// ---------------------------------------------------------------------------
__global__ void __launch_bounds__(256, 2)
scores_wmma(const __half* __restrict__ Q16, const __half* __restrict__ K16,
            const unsigned char* __restrict__ mask,
            __half* __restrict__ E, float* __restrict__ rowsum) {
    extern __shared__ char smraw[];
    __half* sQ = (__half*)smraw;                       // [128][72]
    __half* sK = sQ + 128 * 72;                        // [128][72]
    float* sC = (float*)smraw;                         // [128][136] (aliased)

    const int tid = threadIdx.x;
    const int warp = tid >> 5, wm = warp >> 1, wn = warp & 1;
    const int bh = blockIdx.z;
    const int q0 = blockIdx.y * 128, k0 = blockIdx.x * 128;
    const size_t qb = (size_t)bh * S * HD;
    const int lr = tid >> 3, lc = tid & 7;

#pragma unroll
    for (int it = 0; it < 4; it++) {
        int r = lr + it * 32;
        *(uint4*)&sQ[r * 72 + lc * 8] = *(const uint4*)&Q16[qb + (size_t)(q0 + r) * HD + lc * 8];
        *(uint4*)&sK[r * 72 + lc * 8] = *(const uint4*)&K16[qb + (size_t)(k0 + r) * HD + lc * 8];
    }
    __syncthreads();

    wmma::fragment<wmma::accumulator, 16, 16, 16, float> acc[2][4];
#pragma unroll
    for (int i = 0; i < 2; i++)
#pragma unroll
        for (int j = 0; j < 4; j++) wmma::fill_fragment(acc[i][j], 0.0f);

#pragma unroll
    for (int kk = 0; kk < 64; kk += 16) {
        wmma::fragment<wmma::matrix_a, 16, 16, 16, __half, wmma::row_major> aq[2];
#pragma unroll
        for (int i = 0; i < 2; i++)
            wmma::load_matrix_sync(aq[i], sQ + (wm * 32 + i * 16) * 72 + kk, 72);
#pragma unroll
        for (int j = 0; j < 4; j++) {
            wmma::fragment<wmma::matrix_b, 16, 16, 16, __half, wmma::col_major> bk;
            wmma::load_matrix_sync(bk, sK + (wn * 64 + j * 16) * 72 + kk, 72);
#pragma unroll
            for (int i = 0; i < 2; i++)
                wmma::mma_sync(acc[i][j], aq[i], bk, acc[i][j]);
        }
    }
    __syncthreads();

#pragma unroll
    for (int i = 0; i < 2; i++)
#pragma unroll
        for (int j = 0; j < 4; j++)
            wmma::store_matrix_sync(sC + (wm * 32 + i * 16) * 136 + wn * 64 + j * 16,
                                    acc[i][j], 136, wmma::mem_row_major);
    __syncthreads();

    const unsigned char* mb = mask + (size_t)(bh & (BB - 1)) * S * S;
    __half* eb = E + (size_t)bh * S * S;
#pragma unroll
    for (int it = 0; it < 16; it++) {
        int idx = tid + it * 256;
        int r = idx >> 5, c4 = (idx & 31) * 4;
        int q = q0 + r, kc = k0 + c4;
        float4 v = *(float4*)&sC[r * 136 + c4];
        uchar4 m4 = *(const uchar4*)&mb[(size_t)q * S + kc];
        float e0 = m4.x ? 0.0f : fast_exp2(v.x);
        float e1 = m4.y ? 0.0f : fast_exp2(v.y);
        float e2 = m4.z ? 0.0f : fast_exp2(v.z);
        float e3 = m4.w ? 0.0f : fast_exp2(v.w);
        uint2 u;
        u.x = cvt2h(e0, e1);
        u.y = cvt2h(e2, e3);
        *(uint2*)&eb[(size_t)q * S + kc] = u;
        float rs = warp_sum((e0 + e1) + (e2 + e3));
        if ((tid & 31) == 0) atomicAdd(&rowsum[bh * S + q], rs);
    }
}

// ---------------------------------------------------------------------------
// AV via fp16 HMMA (R12 structure): a = fp16(e) * rr -> attn (fp32, final)
// AND fp16 smem. 1 MMA/tile. 4x2 warp tiling, K-step 32.
// NEW: launch_bounds(256,3) — cap regs at 84 for 3 blocks/SM (occ 24->37%).
// ---------------------------------------------------------------------------
__global__ void __launch_bounds__(256, 3)
av_fp16(const __half* __restrict__ E, const __half* __restrict__ V16,
        const float* __restrict__ rowsum,
        float* __restrict__ attn, float* __restrict__ ctx) {
    __shared__ __half sA[128 * 40];
    __shared__ __half sV[32 * 72];
    __shared__ float rr[128];

    const int tid = threadIdx.x;
    const int warp = tid >> 5, wm = warp >> 1, wn = warp & 1;
    const int bh = blockIdx.y, q0 = blockIdx.x * 128;
    const int b = bh >> 4, h = bh & 15;
    const size_t vb = (size_t)bh * S * HD;
    const __half* eb = E + (size_t)bh * S * S;
    float* ab = attn + (size_t)bh * S * S;   // block-local base; LOCAL offsets
    const int lr = tid >> 3, lc = tid & 7;

    if (tid < 128) rr[tid] = 1.0f / rowsum[bh * S + q0 + tid];
    __syncthreads();

    wmma::fragment<wmma::accumulator, 16, 16, 16, float> acc[2][2];
#pragma unroll
    for (int i = 0; i < 2; i++)
#pragma unroll
        for (int j = 0; j < 2; j++) wmma::fill_fragment(acc[i][j], 0.0f);

    for (int k0 = 0; k0 < S; k0 += 32) {
        // A: 128q x 32k. fp16 e load -> *rr -> fp32 attn store + fp16 smem.
#pragma unroll
        for (int it = 0; it < 4; it++) {
            int r = lr + it * 32;                    // q row 0..127
            size_t p = (size_t)(q0 + r) * S + k0 + lc * 4;
            uint2 ue = *(const uint2*)&eb[p];
            __half2 e01 = *(__half2*)&ue.x, e23 = *(__half2*)&ue.y;
            float2 f01 = __half22float2(e01), f23 = __half22float2(e23);
            float rrq = rr[r];
            float a0 = f01.x * rrq, a1 = f01.y * rrq;
            float a2 = f23.x * rrq, a3 = f23.y * rrq;
            *(float4*)&ab[p] = make_float4(a0, a1, a2, a3);  // final attn
            uint2 ua;
            ua.x = cvt2h(a0, a1);
            ua.y = cvt2h(a2, a3);
            *(uint2*)&sA[r * 40 + lc * 4] = ua;
        }
        // V: 32k x 64d fp16, uint4 (8 halves) per access
        {
            int r = tid >> 3, c8 = (tid & 7) * 8;
            *(uint4*)&sV[r * 72 + c8] = *(const uint4*)&V16[vb + (size_t)(k0 + r) * HD + c8];
        }
        __syncthreads();
#pragma unroll
        for (int kk = 0; kk < 32; kk += 16) {
            wmma::fragment<wmma::matrix_a, 16, 16, 16, __half, wmma::row_major> af[2];
#pragma unroll
            for (int i = 0; i < 2; i++)
                wmma::load_matrix_sync(af[i], sA + (wm * 32 + i * 16) * 40 + kk, 40);
#pragma unroll
            for (int j = 0; j < 2; j++) {
                wmma::fragment<wmma::matrix_b, 16, 16, 16, __half, wmma::row_major> bv;
                wmma::load_matrix_sync(bv, sV + kk * 72 + wn * 32 + j * 16, 72);
#pragma unroll
                for (int i = 0; i < 2; i++)
                    wmma::mma_sync(acc[i][j], af[i], bv, acc[i][j]);
            }
        }
        __syncthreads();
    }

#pragma unroll
    for (int i = 0; i < 2; i++)
#pragma unroll
        for (int j = 0; j < 2; j++) {
            int m = q0 + wm * 32 + i * 16;
            int n = wn * 32 + j * 16;
            float* p = ctx + ((size_t)b * S + m) * DD + h * HD + n;
            wmma::store_matrix_sync(p, acc[i][j], DD, wmma::mem_row_major);
        }
}

// ---------------------------------------------------------------------------
extern "C" void kernel_launch(void* const* d_in, const int* in_sizes, int n_in,
                              void* d_out, int out_size) {
    const float* query = (const float*)d_in[0];
    const float* key   = (const float*)d_in[1];
    const float* value = (const float*)d_in[2];
    const void*  mask  = d_in[3];
    const float* Wq = (const float*)d_in[4];
    const float* bq = (const float*)d_in[5];
    const float* Wk = (const float*)d_in[6];
    const float* bk = (const float*)d_in[7];
    const float* Wv = (const float*)d_in[8];
    const float* bv = (const float*)d_in[9];

    float* ctx = (float*)d_out;

    __half *q16, *k16, *v16, *e16;
    float *rowsum, *attn_fallback;
    unsigned char* mu8;
    cudaGetSymbolAddress((void**)&q16, g_q16);
    cudaGetSymbolAddress((void**)&k16, g_k16);
    cudaGetSymbolAddress((void**)&v16, g_v16);
    cudaGetSymbolAddress((void**)&e16, g_e16);
    cudaGetSymbolAddress((void**)&mu8, g_mask_u8);
    cudaGetSymbolAddress((void**)&rowsum, g_rowsum);
    cudaGetSymbolAddress((void**)&attn_fallback, g_attn_scratch);

    const long long CTX_ELEMS  = (long long)BB * S * DD;
    const long long ATTN_ELEMS = (long long)BH * S * S;
    float* attn = ((long long)out_size >= CTX_ELEMS + ATTN_ELEMS)
                      ? (ctx + CTX_ELEMS) : attn_fallback;

    const int PROJ_SMEM   = 128 * 136 * 4;          // 69632
    const int SCORES_SMEM = 128 * 136 * 4;          // 69632 (sC dominates)
    cudaFuncSetAttribute(proj_wmma, cudaFuncAttributeMaxDynamicSharedMemorySize, PROJ_SMEM);
    cudaFuncSetAttribute(scores_wmma, cudaFuncAttributeMaxDynamicSharedMemorySize, SCORES_SMEM);

    detect_mask_kernel<<<1, 256>>>((const unsigned int*)mask);
    convert_mask_kernel<<<MASK_N / 256, 256>>>(mask, mu8);
    cudaMemsetAsync(rowsum, 0, BH * S * sizeof(float));

    proj_wmma<<<dim3(DD / 128, MROWS / 128, 3), 256, PROJ_SMEM>>>(
        query, key, value, Wq, Wk, Wv, bq, bk, bv, q16, k16, v16);

    scores_wmma<<<dim3(S / 128, S / 128, BH), 256, SCORES_SMEM>>>(
        q16, k16, mu8, e16, rowsum);

    av_fp16<<<dim3(S / 128, BH), 256>>>(e16, v16, rowsum, attn, ctx);
}

// round 15
// speedup vs baseline: 1.0705x; 1.0705x over previous
#include <cuda_runtime.h>
#include <cuda_bf16.h>
#include <cuda_fp16.h>
#include <mma.h>
#include <math_constants.h>

using namespace nvcuda;

// Problem constants
#define BB 2
#define S  2048
#define DD 1024
#define H  16
#define HD 64
#define BH (BB*H)       // 32
#define MROWS (BB*S)    // 4096
#define MASK_N (BB*S*S) // 8,388,608

// Scratch (device globals: allocation-free)
__device__ __half g_q16[BH * S * HD];          // Q (scale folded), fp16
__device__ __half g_k16[BH * S * HD];          // K, fp16
__device__ __half g_v16[BH * S * HD];          // V, fp16
__device__ __half g_e16[(size_t)BH * S * S];   // exp(scores), fp16 (268MB)
__device__ float g_rowsum[BH * S];
__device__ unsigned char g_mask_u8[MASK_N];
__device__ int g_mask_mode;
__device__ float g_attn_scratch[(size_t)BH * S * S]; // fallback if d_out only holds ctx

// ---------------------------------------------------------------------------
// exp2 via magic-constant round + deg-4 Taylor (feeds fp16 storage).
// ---------------------------------------------------------------------------
__device__ __forceinline__ float fast_exp2(float y) {
    y = fminf(fmaxf(y, -24.0f), 15.5f);
    float z = y + 12582912.0f;                 // 0x1.8p23: round(y) in low bits
    float r = z - 12582912.0f;                 // exact round(y)
    float f = y - r;                           // exact, in [-0.5, 0.5]
    float sc = __int_as_float((__float_as_int(z) + 127) << 23);  // 2^r
    float p = 9.6181291e-3f;                   // ln2^4/24
    p = fmaf(p, f, 5.5504109e-2f);             // ln2^3/6
    p = fmaf(p, f, 2.4022651e-1f);             // ln2^2/2
    p = fmaf(p, f, 6.9314718e-1f);             // ln2
    p = fmaf(p, f, 1.0f);
    return p * sc;
}

__device__ __forceinline__ void split_bf(float x, __nv_bfloat16& h, __nv_bfloat16& l) {
    h = __float2bfloat16(x);
    l = __float2bfloat16(x - __bfloat162float(h));
}
__device__ __forceinline__ unsigned cvt2h(float a, float b) {
    __half2 t = __float22half2_rn(make_float2(a, b));
    return *(unsigned*)&t;
}
// fp32 warp reduce: redux.f32 does NOT exist on sm_103 — shfl tree.
__device__ __forceinline__ float warp_sum(float v) {
#pragma unroll
    for (int o = 16; o > 0; o >>= 1) v += __shfl_xor_sync(0xffffffffu, v, o);
    return v;
}

// ---------------------------------------------------------------------------
// Mask dtype detection + conversion (proven R2-R14)
// ---------------------------------------------------------------------------
__global__ void detect_mask_kernel(const unsigned int* __restrict__ w) {
    __shared__ int s_int, s_float;
    if (threadIdx.x == 0) { s_int = 1; s_float = 1; }
    __syncthreads();
    int li = 1, lf = 1;
    for (int i = threadIdx.x; i < 2048; i += 256) {
        unsigned int x = w[i];
        if (x != 0u && x != 1u) li = 0;
        if (x != 0u && x != 0x3f800000u) lf = 0;
    }
    if (!li) atomicAnd(&s_int, 0);
    if (!lf) atomicAnd(&s_float, 0);
    __syncthreads();
    if (threadIdx.x == 0) g_mask_mode = s_int ? 1 : (s_float ? 2 : 0);
}

__global__ void convert_mask_kernel(const void* __restrict__ mraw,
                                    unsigned char* __restrict__ mu8) {
    int i = blockIdx.x * blockDim.x + threadIdx.x;
    if (i >= MASK_N) return;
    int mode = g_mask_mode;
    unsigned char v;
    if (mode == 0)      v = ((const unsigned char*)mraw)[i];
    else if (mode == 1) v = (unsigned char)(((const int*)mraw)[i] != 0);
    else                v = (unsigned char)(((const float*)mraw)[i] != 0.0f);
    mu8[i] = v;
}

// ---------------------------------------------------------------------------
// Projection (all 3 via z): C = X*W^T + bias, *scale. GEMM in bf16 hi/lo;
// outputs single fp16 head-split. Q (z=0) folds 0.125*log2(e).
// ---------------------------------------------------------------------------
__global__ void __launch_bounds__(256, 2)
proj_wmma(const float* __restrict__ X0, const float* __restrict__ X1, const float* __restrict__ X2,
          const float* __restrict__ W0, const float* __restrict__ W1, const float* __restrict__ W2,
          const float* __restrict__ B0, const float* __restrict__ B1, const float* __restrict__ B2,
          __half* __restrict__ O0, __half* __restrict__ O1, __half* __restrict__ O2) {
    extern __shared__ char smraw[];
    __nv_bfloat16* sAh = (__nv_bfloat16*)smraw;        // [128][40]
    __nv_bfloat16* sAl = sAh + 128 * 40;
    __nv_bfloat16* sBh = sAl + 128 * 40;
    __nv_bfloat16* sBl = sBh + 128 * 40;
    float* sC = (float*)smraw;                         // [128][136] (aliased)

    const float *X, *W, *Bv; __half* O; float scale;
    const int mode = blockIdx.z;
    if (mode == 0)      { X = X0; W = W0; Bv = B0; O = O0;
                          scale = 0.18033688011111378f; }   // 0.125*log2(e)
    else if (mode == 1) { X = X1; W = W1; Bv = B1; O = O1; scale = 1.0f; }
    else                { X = X2; W = W2; Bv = B2; O = O2; scale = 1.0f; }

    const int tid = threadIdx.x;
    const int warp = tid >> 5, wm = warp >> 1, wn = warp & 1;
    const int m0 = blockIdx.y * 128, n0 = blockIdx.x * 128;
    const int lr = tid >> 3, lc = tid & 7;

    wmma::fragment<wmma::accumulator, 16, 16, 16, float> acc[2][4];
#pragma unroll
    for (int i = 0; i < 2; i++)
#pragma unroll
        for (int j = 0; j < 4; j++) wmma::fill_fragment(acc[i][j], 0.0f);

    for (int k0 = 0; k0 < DD; k0 += 32) {
#pragma unroll
        for (int it = 0; it < 4; it++) {
            int r = lr + it * 32;
            float4 xv = *(const float4*)(X + (size_t)(m0 + r) * DD + k0 + lc * 4);
            float4 wv = *(const float4*)(W + (size_t)(n0 + r) * DD + k0 + lc * 4);
            int sa = r * 40 + lc * 4;
            float xs[4] = {xv.x, xv.y, xv.z, xv.w};
            float ws[4] = {wv.x, wv.y, wv.z, wv.w};
#pragma unroll
            for (int j = 0; j < 4; j++) {
                __nv_bfloat16 h, l;
                split_bf(xs[j], h, l); sAh[sa + j] = h; sAl[sa + j] = l;
                split_bf(ws[j], h, l); sBh[sa + j] = h; sBl[sa + j] = l;
            }
        }
        __syncthreads();
#pragma unroll
        for (int kk = 0; kk < 32; kk += 16) {
            wmma::fragment<wmma::matrix_a, 16, 16, 16, __nv_bfloat16, wmma::row_major> ah[2], al[2];
#pragma unroll
            for (int i = 0; i < 2; i++) {
                wmma::load_matrix_sync(ah[i], sAh + (wm * 32 + i * 16) * 40 + kk, 40);
                wmma::load_matrix_sync(al[i], sAl + (wm * 32 + i * 16) * 40 + kk, 40);
            }
#pragma unroll
            for (int j = 0; j < 4; j++) {
                wmma::fragment<wmma::matrix_b, 16, 16, 16, __nv_bfloat16, wmma::col_major> bh_, bl_;
                wmma::load_matrix_sync(bh_, sBh + (wn * 64 + j * 16) * 40 + kk, 40);
                wmma::load_matrix_sync(bl_, sBl + (wn * 64 + j * 16) * 40 + kk, 40);
#pragma unroll
                for (int i = 0; i < 2; i++) {
                    wmma::mma_sync(acc[i][j], ah[i], bh_, acc[i][j]);
                    wmma::mma_sync(acc[i][j], ah[i], bl_, acc[i][j]);
                    wmma::mma_sync(acc[i][j], al[i], bh_, acc[i][j]);
                }
            }
        }
        __syncthreads();
    }

#pragma unroll
    for (int i = 0; i < 2; i++)
#pragma unroll
        for (int j = 0; j < 4; j++)
            wmma::store_matrix_sync(sC + (wm * 32 + i * 16) * 136 + wn * 64 + j * 16,
                                    acc[i][j], 136, wmma::mem_row_major);
    __syncthreads();

#pragma unroll
    for (int it = 0; it < 16; it++) {
        int idx = tid + it * 256;
        int r = idx >> 5, c4 = (idx & 31) * 4;
        float4 v = *(float4*)&sC[r * 136 + c4];
        float4 bb = *(const float4*)&Bv[n0 + c4];
        int gc = n0 + c4;
        int hh = gc >> 6, d = gc & 63;
        int gr = m0 + r;
        int b = gr >> 11, s = gr & (S - 1);
        size_t p = (((size_t)(b * H + hh)) * S + s) * HD + d;
        uint2 u;
        u.x = cvt2h((v.x + bb.x) * scale, (v.y + bb.y) * scale);
        u.y = cvt2h((v.z + bb.z) * scale, (v.w + bb.w) * scale);
        *(uint2*)&O[p] = u;
    }
}

// ---------------------------------------------------------------------------
// Scores (R12-proven, ~232us): 128q x 128k tile, d=64 resident, single fp16
// MMA per k-step. Block epilogue with sC round-trip.
// ---------------------------------------------------------------------------
__global__ void __launch_bounds__(256, 2)
scores_wmma(const __half* __restrict__ Q16, const __half* __restrict__ K16,
            const unsigned char* __restrict__ mask,
            __half* __restrict__ E, float* __restrict__ rowsum) {
    extern __shared__ char smraw[];
    __half* sQ = (__half*)smraw;                       // [128][72]
    __half* sK = sQ + 128 * 72;                        // [128][72]
    float* sC = (float*)smraw;                         // [128][136] (aliased)

    const int tid = threadIdx.x;
    const int warp = tid >> 5, wm = warp >> 1, wn = warp & 1;
    const int bh = blockIdx.z;
    const int q0 = blockIdx.y * 128, k0 = blockIdx.x * 128;
    const size_t qb = (size_t)bh * S * HD;
    const int lr = tid >> 3, lc = tid & 7;

#pragma unroll
    for (int it = 0; it < 4; it++) {
        int r = lr + it * 32;
        *(uint4*)&sQ[r * 72 + lc * 8] = *(const uint4*)&Q16[qb + (size_t)(q0 + r) * HD + lc * 8];
        *(uint4*)&sK[r * 72 + lc * 8] = *(const uint4*)&K16[qb + (size_t)(k0 + r) * HD + lc * 8];
    }
    __syncthreads();

    wmma::fragment<wmma::accumulator, 16, 16, 16, float> acc[2][4];
#pragma unroll
    for (int i = 0; i < 2; i++)
#pragma unroll
        for (int j = 0; j < 4; j++) wmma::fill_fragment(acc[i][j], 0.0f);

#pragma unroll
    for (int kk = 0; kk < 64; kk += 16) {
        wmma::fragment<wmma::matrix_a, 16, 16, 16, __half, wmma::row_major> aq[2];
#pragma unroll
        for (int i = 0; i < 2; i++)
            wmma::load_matrix_sync(aq[i], sQ + (wm * 32 + i * 16) * 72 + kk, 72);
#pragma unroll
        for (int j = 0; j < 4; j++) {
            wmma::fragment<wmma::matrix_b, 16, 16, 16, __half, wmma::col_major> bk;
            wmma::load_matrix_sync(bk, sK + (wn * 64 + j * 16) * 72 + kk, 72);
#pragma unroll
            for (int i = 0; i < 2; i++)
                wmma::mma_sync(acc[i][j], aq[i], bk, acc[i][j]);
        }
    }
    __syncthreads();

#pragma unroll
    for (int i = 0; i < 2; i++)
#pragma unroll
        for (int j = 0; j < 4; j++)
            wmma::store_matrix_sync(sC + (wm * 32 + i * 16) * 136 + wn * 64 + j * 16,
                                    acc[i][j], 136, wmma::mem_row_major);
    __syncthreads();

    const unsigned char* mb = mask + (size_t)(bh & (BB - 1)) * S * S;
    __half* eb = E + (size_t)bh * S * S;
#pragma unroll
    for (int it = 0; it < 16; it++) {
        int idx = tid + it * 256;
        int r = idx >> 5, c4 = (idx & 31) * 4;
        int q = q0 + r, kc = k0 + c4;
        float4 v = *(float4*)&sC[r * 136 + c4];
        uchar4 m4 = *(const uchar4*)&mb[(size_t)q * S + kc];
        float e0 = m4.x ? 0.0f : fast_exp2(v.x);
        float e1 = m4.y ? 0.0f : fast_exp2(v.y);
        float e2 = m4.z ? 0.0f : fast_exp2(v.z);
        float e3 = m4.w ? 0.0f : fast_exp2(v.w);
        uint2 u;
        u.x = cvt2h(e0, e1);
        u.y = cvt2h(e2, e3);
        *(uint2*)&eb[(size_t)q * S + kc] = u;
        float rs = warp_sum((e0 + e1) + (e2 + e3));
        if ((tid & 31) == 0) atomicAdd(&rowsum[bh * S + q], rs);
    }
}

// ---------------------------------------------------------------------------
// AV via fp16 HMMA: a = fp16(e) * rr -> attn (fp32, final) AND fp16 smem.
// 1 MMA/tile. R12-proven 4x2 warp tiling + acc[2][2]; K-step widened to 64
// (halves syncthreads; registers unchanged). launch_bounds back to (256,2).
// ---------------------------------------------------------------------------
__global__ void __launch_bounds__(256, 2)
av_fp16(const __half* __restrict__ E, const __half* __restrict__ V16,
        const float* __restrict__ rowsum,
        float* __restrict__ attn, float* __restrict__ ctx) {
    __shared__ __half sA[128 * 72];   // [128][72], cols 0..63 used
    __shared__ __half sV[64 * 72];    // [64][72],  cols 0..63 used
    __shared__ float rr[128];

    const int tid = threadIdx.x;
    const int warp = tid >> 5, wm = warp >> 1, wn = warp & 1;
    const int bh = blockIdx.y, q0 = blockIdx.x * 128;
    const int b = bh >> 4, h = bh & 15;
    const size_t vb = (size_t)bh * S * HD;
    const __half* eb = E + (size_t)bh * S * S;
    float* ab = attn + (size_t)bh * S * S;   // block-local base; LOCAL offsets
    const int lr = tid >> 4, lc = tid & 15;  // A-path: 16 float4 slots per row

    if (tid < 128) rr[tid] = 1.0f / rowsum[bh * S + q0 + tid];
    __syncthreads();

    wmma::fragment<wmma::accumulator, 16, 16, 16, float> acc[2][2];
#pragma unroll
    for (int i = 0; i < 2; i++)
#pragma unroll
        for (int j = 0; j < 2; j++) wmma::fill_fragment(acc[i][j], 0.0f);

    for (int k0 = 0; k0 < S; k0 += 64) {
        // A: 128q x 64k. 2048 float4 slots, 8 per thread.
#pragma unroll
        for (int it = 0; it < 8; it++) {
            int r = lr + it * 16;                    // q row 0..127
            size_t p = (size_t)(q0 + r) * S + k0 + lc * 4;
            uint2 ue = *(const uint2*)&eb[p];
            __half2 e01 = *(__half2*)&ue.x, e23 = *(__half2*)&ue.y;
            float2 f01 = __half22float2(e01), f23 = __half22float2(e23);
            float rrq = rr[r];
            float a0 = f01.x * rrq, a1 = f01.y * rrq;
            float a2 = f23.x * rrq, a3 = f23.y * rrq;
            *(float4*)&ab[p] = make_float4(a0, a1, a2, a3);  // final attn
            uint2 ua;
            ua.x = cvt2h(a0, a1);
            ua.y = cvt2h(a2, a3);
            *(uint2*)&sA[r * 72 + lc * 4] = ua;
        }
        // V: 64k x 64d fp16, uint4 (8 halves) per access: 512 slots, 2/thread
#pragma unroll
        for (int it = 0; it < 2; it++) {
            int slot = tid + it * 256;
            int r = slot >> 3, c8 = (slot & 7) * 8;
            *(uint4*)&sV[r * 72 + c8] = *(const uint4*)&V16[vb + (size_t)(k0 + r) * HD + c8];
        }
        __syncthreads();
#pragma unroll
        for (int kk = 0; kk < 64; kk += 16) {
            wmma::fragment<wmma::matrix_a, 16, 16, 16, __half, wmma::row_major> af[2];
#pragma unroll
            for (int i = 0; i < 2; i++)
                wmma::load_matrix_sync(af[i], sA + (wm * 32 + i * 16) * 72 + kk, 72);
#pragma unroll
            for (int j = 0; j < 2; j++) {
                wmma::fragment<wmma::matrix_b, 16, 16, 16, __half, wmma::row_major> bv;
                wmma::load_matrix_sync(bv, sV + kk * 72 + wn * 32 + j * 16, 72);
#pragma unroll
                for (int i = 0; i < 2; i++)
                    wmma::mma_sync(acc[i][j], af[i], bv, acc[i][j]);
            }
        }
        __syncthreads();
    }

#pragma unroll
    for (int i = 0; i < 2; i++)
#pragma unroll
        for (int j = 0; j < 2; j++) {
            int m = q0 + wm * 32 + i * 16;
            int n = wn * 32 + j * 16;
            float* p = ctx + ((size_t)b * S + m) * DD + h * HD + n;
            wmma::store_matrix_sync(p, acc[i][j], DD, wmma::mem_row_major);
        }
}

// ---------------------------------------------------------------------------
extern "C" void kernel_launch(void* const* d_in, const int* in_sizes, int n_in,
                              void* d_out, int out_size) {
    const float* query = (const float*)d_in[0];
    const float* key   = (const float*)d_in[1];
    const float* value = (const float*)d_in[2];
    const void*  mask  = d_in[3];
    const float* Wq = (const float*)d_in[4];
    const float* bq = (const float*)d_in[5];
    const float* Wk = (const float*)d_in[6];
    const float* bk = (const float*)d_in[7];
    const float* Wv = (const float*)d_in[8];
    const float* bv = (const float*)d_in[9];

    float* ctx = (float*)d_out;

    __half *q16, *k16, *v16, *e16;
    float *rowsum, *attn_fallback;
    unsigned char* mu8;
    cudaGetSymbolAddress((void**)&q16, g_q16);
    cudaGetSymbolAddress((void**)&k16, g_k16);
    cudaGetSymbolAddress((void**)&v16, g_v16);
    cudaGetSymbolAddress((void**)&e16, g_e16);
    cudaGetSymbolAddress((void**)&mu8, g_mask_u8);
    cudaGetSymbolAddress((void**)&rowsum, g_rowsum);
    cudaGetSymbolAddress((void**)&attn_fallback, g_attn_scratch);

    const long long CTX_ELEMS  = (long long)BB * S * DD;
    const long long ATTN_ELEMS = (long long)BH * S * S;
    float* attn = ((long long)out_size >= CTX_ELEMS + ATTN_ELEMS)
                      ? (ctx + CTX_ELEMS) : attn_fallback;

    const int PROJ_SMEM   = 128 * 136 * 4;          // 69632
    const int SCORES_SMEM = 128 * 136 * 4;          // 69632 (sC dominates)
    cudaFuncSetAttribute(proj_wmma, cudaFuncAttributeMaxDynamicSharedMemorySize, PROJ_SMEM);
    cudaFuncSetAttribute(scores_wmma, cudaFuncAttributeMaxDynamicSharedMemorySize, SCORES_SMEM);

    detect_mask_kernel<<<1, 256>>>((const unsigned int*)mask);
    convert_mask_kernel<<<MASK_N / 256, 256>>>(mask, mu8);
    cudaMemsetAsync(rowsum, 0, BH * S * sizeof(float));

    proj_wmma<<<dim3(DD / 128, MROWS / 128, 3), 256, PROJ_SMEM>>>(
        query, key, value, Wq, Wk, Wv, bq, bk, bv, q16, k16, v16);

    scores_wmma<<<dim3(S / 128, S / 128, BH), 256, SCORES_SMEM>>>(
        q16, k16, mu8, e16, rowsum);

    av_fp16<<<dim3(S / 128, BH), 256>>>(e16, v16, rowsum, attn, ctx);
}

// round 16
// speedup vs baseline: 1.1955x; 1.1168x over previous
#include <cuda_runtime.h>
#include <cuda_bf16.h>
#include <cuda_fp16.h>
#include <mma.h>
#include <math_constants.h>

using namespace nvcuda;

// Problem constants
#define BB 2
#define S  2048
#define DD 1024
#define H  16
#define HD 64
#define BH (BB*H)       // 32
#define MROWS (BB*S)    // 4096
#define MASK_N (BB*S*S) // 8,388,608

// Scratch (device globals: allocation-free)
__device__ __half g_q16[BH * S * HD];          // Q (scale folded), fp16
__device__ __half g_k16[BH * S * HD];          // K, fp16
__device__ __half g_v16[BH * S * HD];          // V, fp16
__device__ __half g_e16[(size_t)BH * S * S];   // exp(scores), fp16 (268MB)
__device__ float g_rowsum[BH * S];
__device__ unsigned char g_mask_u8[MASK_N];
__device__ int g_mask_mode;
__device__ float g_attn_scratch[(size_t)BH * S * S]; // fallback if d_out only holds ctx

// ---------------------------------------------------------------------------
// exp2 via magic-constant round + deg-4 Taylor (feeds fp16 storage).
// ---------------------------------------------------------------------------
__device__ __forceinline__ float fast_exp2(float y) {
    y = fminf(fmaxf(y, -24.0f), 15.5f);
    float z = y + 12582912.0f;                 // 0x1.8p23: round(y) in low bits
    float r = z - 12582912.0f;                 // exact round(y)
    float f = y - r;                           // exact, in [-0.5, 0.5]
    float sc = __int_as_float((__float_as_int(z) + 127) << 23);  // 2^r
    float p = 9.6181291e-3f;                   // ln2^4/24
    p = fmaf(p, f, 5.5504109e-2f);             // ln2^3/6
    p = fmaf(p, f, 2.4022651e-1f);             // ln2^2/2
    p = fmaf(p, f, 6.9314718e-1f);             // ln2
    p = fmaf(p, f, 1.0f);
    return p * sc;
}

__device__ __forceinline__ void split_h(float x, __half& h, __half& l) {
    h = __float2half_rn(x);
    l = __float2half_rn(x - __half2float(h));
}
__device__ __forceinline__ unsigned cvt2h(float a, float b) {
    __half2 t = __float22half2_rn(make_float2(a, b));
    return *(unsigned*)&t;
}
// fp32 warp reduce: redux.f32 does NOT exist on sm_103 — shfl tree.
__device__ __forceinline__ float warp_sum(float v) {
#pragma unroll
    for (int o = 16; o > 0; o >>= 1) v += __shfl_xor_sync(0xffffffffu, v, o);
    return v;
}

// ---------------------------------------------------------------------------
// Mask dtype detection + conversion (proven R2-R15)
// ---------------------------------------------------------------------------
__global__ void detect_mask_kernel(const unsigned int* __restrict__ w) {
    __shared__ int s_int, s_float;
    if (threadIdx.x == 0) { s_int = 1; s_float = 1; }
    __syncthreads();
    int li = 1, lf = 1;
    for (int i = threadIdx.x; i < 2048; i += 256) {
        unsigned int x = w[i];
        if (x != 0u && x != 1u) li = 0;
        if (x != 0u && x != 0x3f800000u) lf = 0;
    }
    if (!li) atomicAnd(&s_int, 0);
    if (!lf) atomicAnd(&s_float, 0);
    __syncthreads();
    if (threadIdx.x == 0) g_mask_mode = s_int ? 1 : (s_float ? 2 : 0);
}

__global__ void convert_mask_kernel(const void* __restrict__ mraw,
                                    unsigned char* __restrict__ mu8) {
    int i = blockIdx.x * blockDim.x + threadIdx.x;
    if (i >= MASK_N) return;
    int mode = g_mask_mode;
    unsigned char v;
    if (mode == 0)      v = ((const unsigned char*)mraw)[i];
    else if (mode == 1) v = (unsigned char)(((const int*)mraw)[i] != 0);
    else                v = (unsigned char)(((const float*)mraw)[i] != 0.0f);
    mu8[i] = v;
}

// ---------------------------------------------------------------------------
// Projection (all 3 via z): C = X*W^T + bias, *scale. X single fp16,
// W fp16 hi/lo => 2 MMAs per tile. Outputs single fp16 head-split.
// Q (z=0) folds 0.125*log2(e).
// ---------------------------------------------------------------------------
__global__ void __launch_bounds__(256, 2)
proj_wmma(const float* __restrict__ X0, const float* __restrict__ X1, const float* __restrict__ X2,
          const float* __restrict__ W0, const float* __restrict__ W1, const float* __restrict__ W2,
          const float* __restrict__ B0, const float* __restrict__ B1, const float* __restrict__ B2,
          __half* __restrict__ O0, __half* __restrict__ O1, __half* __restrict__ O2) {
    extern __shared__ char smraw[];
    __half* sX  = (__half*)smraw;                      // [128][40]
    __half* sWh = sX + 128 * 40;                       // [128][40]
    __half* sWl = sWh + 128 * 40;                      // [128][40]
    float* sC = (float*)smraw;                         // [128][136] (aliased)

    const float *X, *W, *Bv; __half* O; float scale;
    const int mode = blockIdx.z;
    if (mode == 0)      { X = X0; W = W0; Bv = B0; O = O0;
                          scale = 0.18033688011111378f; }   // 0.125*log2(e)
    else if (mode == 1) { X = X1; W = W1; Bv = B1; O = O1; scale = 1.0f; }
    else                { X = X2; W = W2; Bv = B2; O = O2; scale = 1.0f; }

    const int tid = threadIdx.x;
    const int warp = tid >> 5, wm = warp >> 1, wn = warp & 1;
    const int m0 = blockIdx.y * 128, n0 = blockIdx.x * 128;
    const int lr = tid >> 3, lc = tid & 7;

    wmma::fragment<wmma::accumulator, 16, 16, 16, float> acc[2][4];
#pragma unroll
    for (int i = 0; i < 2; i++)
#pragma unroll
        for (int j = 0; j < 4; j++) wmma::fill_fragment(acc[i][j], 0.0f);

    for (int k0 = 0; k0 < DD; k0 += 32) {
#pragma unroll
        for (int it = 0; it < 4; it++) {
            int r = lr + it * 32;
            float4 xv = *(const float4*)(X + (size_t)(m0 + r) * DD + k0 + lc * 4);
            float4 wv = *(const float4*)(W + (size_t)(n0 + r) * DD + k0 + lc * 4);
            int sa = r * 40 + lc * 4;
            // X: single fp16
            uint2 ux;
            ux.x = cvt2h(xv.x, xv.y);
            ux.y = cvt2h(xv.z, xv.w);
            *(uint2*)&sX[sa] = ux;
            // W: fp16 hi/lo
            float ws[4] = {wv.x, wv.y, wv.z, wv.w};
#pragma unroll
            for (int j = 0; j < 4; j++) {
                __half h, l;
                split_h(ws[j], h, l);
                sWh[sa + j] = h; sWl[sa + j] = l;
            }
        }
        __syncthreads();
#pragma unroll
        for (int kk = 0; kk < 32; kk += 16) {
            wmma::fragment<wmma::matrix_a, 16, 16, 16, __half, wmma::row_major> ax[2];
#pragma unroll
            for (int i = 0; i < 2; i++)
                wmma::load_matrix_sync(ax[i], sX + (wm * 32 + i * 16) * 40 + kk, 40);
#pragma unroll
            for (int j = 0; j < 4; j++) {
                wmma::fragment<wmma::matrix_b, 16, 16, 16, __half, wmma::col_major> bh_, bl_;
                wmma::load_matrix_sync(bh_, sWh + (wn * 64 + j * 16) * 40 + kk, 40);
                wmma::load_matrix_sync(bl_, sWl + (wn * 64 + j * 16) * 40 + kk, 40);
#pragma unroll
                for (int i = 0; i < 2; i++) {
                    wmma::mma_sync(acc[i][j], ax[i], bh_, acc[i][j]);
                    wmma::mma_sync(acc[i][j], ax[i], bl_, acc[i][j]);
                }
            }
        }
        __syncthreads();
    }

#pragma unroll
    for (int i = 0; i < 2; i++)
#pragma unroll
        for (int j = 0; j < 4; j++)
            wmma::store_matrix_sync(sC + (wm * 32 + i * 16) * 136 + wn * 64 + j * 16,
                                    acc[i][j], 136, wmma::mem_row_major);
    __syncthreads();

#pragma unroll
    for (int it = 0; it < 16; it++) {
        int idx = tid + it * 256;
        int r = idx >> 5, c4 = (idx & 31) * 4;
        float4 v = *(float4*)&sC[r * 136 + c4];
        float4 bb = *(const float4*)&Bv[n0 + c4];
        int gc = n0 + c4;
        int hh = gc >> 6, d = gc & 63;
        int gr = m0 + r;
        int b = gr >> 11, s = gr & (S - 1);
        size_t p = (((size_t)(b * H + hh)) * S + s) * HD + d;
        uint2 u;
        u.x = cvt2h((v.x + bb.x) * scale, (v.y + bb.y) * scale);
        u.y = cvt2h((v.z + bb.z) * scale, (v.w + bb.w) * scale);
        *(uint2*)&O[p] = u;
    }
}

// ---------------------------------------------------------------------------
// Scores (R12-proven, ~232us): 128q x 128k tile, d=64 resident, single fp16
// MMA per k-step. Block epilogue with sC round-trip.
// ---------------------------------------------------------------------------
__global__ void __launch_bounds__(256, 2)
scores_wmma(const __half* __restrict__ Q16, const __half* __restrict__ K16,
            const unsigned char* __restrict__ mask,
            __half* __restrict__ E, float* __restrict__ rowsum) {
    extern __shared__ char smraw[];
    __half* sQ = (__half*)smraw;                       // [128][72]
    __half* sK = sQ + 128 * 72;                        // [128][72]
    float* sC = (float*)smraw;                         // [128][136] (aliased)

    const int tid = threadIdx.x;
    const int warp = tid >> 5, wm = warp >> 1, wn = warp & 1;
    const int bh = blockIdx.z;
    const int q0 = blockIdx.y * 128, k0 = blockIdx.x * 128;
    const size_t qb = (size_t)bh * S * HD;
    const int lr = tid >> 3, lc = tid & 7;

#pragma unroll
    for (int it = 0; it < 4; it++) {
        int r = lr + it * 32;
        *(uint4*)&sQ[r * 72 + lc * 8] = *(const uint4*)&Q16[qb + (size_t)(q0 + r) * HD + lc * 8];
        *(uint4*)&sK[r * 72 + lc * 8] = *(const uint4*)&K16[qb + (size_t)(k0 + r) * HD + lc * 8];
    }
    __syncthreads();

    wmma::fragment<wmma::accumulator, 16, 16, 16, float> acc[2][4];
#pragma unroll
    for (int i = 0; i < 2; i++)
#pragma unroll
        for (int j = 0; j < 4; j++) wmma::fill_fragment(acc[i][j], 0.0f);

#pragma unroll
    for (int kk = 0; kk < 64; kk += 16) {
        wmma::fragment<wmma::matrix_a, 16, 16, 16, __half, wmma::row_major> aq[2];
#pragma unroll
        for (int i = 0; i < 2; i++)
            wmma::load_matrix_sync(aq[i], sQ + (wm * 32 + i * 16) * 72 + kk, 72);
#pragma unroll
        for (int j = 0; j < 4; j++) {
            wmma::fragment<wmma::matrix_b, 16, 16, 16, __half, wmma::col_major> bk;
            wmma::load_matrix_sync(bk, sK + (wn * 64 + j * 16) * 72 + kk, 72);
#pragma unroll
            for (int i = 0; i < 2; i++)
                wmma::mma_sync(acc[i][j], aq[i], bk, acc[i][j]);
        }
    }
    __syncthreads();

#pragma unroll
    for (int i = 0; i < 2; i++)
#pragma unroll
        for (int j = 0; j < 4; j++)
            wmma::store_matrix_sync(sC + (wm * 32 + i * 16) * 136 + wn * 64 + j * 16,
                                    acc[i][j], 136, wmma::mem_row_major);
    __syncthreads();

    const unsigned char* mb = mask + (size_t)(bh & (BB - 1)) * S * S;
    __half* eb = E + (size_t)bh * S * S;
#pragma unroll
    for (int it = 0; it < 16; it++) {
        int idx = tid + it * 256;
        int r = idx >> 5, c4 = (idx & 31) * 4;
        int q = q0 + r, kc = k0 + c4;
        float4 v = *(float4*)&sC[r * 136 + c4];
        uchar4 m4 = *(const uchar4*)&mb[(size_t)q * S + kc];
        float e0 = m4.x ? 0.0f : fast_exp2(v.x);
        float e1 = m4.y ? 0.0f : fast_exp2(v.y);
        float e2 = m4.z ? 0.0f : fast_exp2(v.z);
        float e3 = m4.w ? 0.0f : fast_exp2(v.w);
        uint2 u;
        u.x = cvt2h(e0, e1);
        u.y = cvt2h(e2, e3);
        *(uint2*)&eb[(size_t)q * S + kc] = u;
        float rs = warp_sum((e0 + e1) + (e2 + e3));
        if ((tid & 31) == 0) atomicAdd(&rowsum[bh * S + q], rs);
    }
}

// ---------------------------------------------------------------------------
// AV via fp16 HMMA (R15-proven): a = fp16(e) * rr -> attn (fp32, final) AND
// fp16 smem. 1 MMA/tile. 4x2 warp tiling, K-step 64.
// ---------------------------------------------------------------------------
__global__ void __launch_bounds__(256, 2)
av_fp16(const __half* __restrict__ E, const __half* __restrict__ V16,
        const float* __restrict__ rowsum,
        float* __restrict__ attn, float* __restrict__ ctx) {
    __shared__ __half sA[128 * 72];   // [128][72], cols 0..63 used
    __shared__ __half sV[64 * 72];    // [64][72],  cols 0..63 used
    __shared__ float rr[128];

    const int tid = threadIdx.x;
    const int warp = tid >> 5, wm = warp >> 1, wn = warp & 1;
    const int bh = blockIdx.y, q0 = blockIdx.x * 128;
    const int b = bh >> 4, h = bh & 15;
    const size_t vb = (size_t)bh * S * HD;
    const __half* eb = E + (size_t)bh * S * S;
    float* ab = attn + (size_t)bh * S * S;   // block-local base; LOCAL offsets
    const int lr = tid >> 4, lc = tid & 15;  // A-path: 16 float4 slots per row

    if (tid < 128) rr[tid] = 1.0f / rowsum[bh * S + q0 + tid];
    __syncthreads();

    wmma::fragment<wmma::accumulator, 16, 16, 16, float> acc[2][2];
#pragma unroll
    for (int i = 0; i < 2; i++)
#pragma unroll
        for (int j = 0; j < 2; j++) wmma::fill_fragment(acc[i][j], 0.0f);

    for (int k0 = 0; k0 < S; k0 += 64) {
        // A: 128q x 64k. 2048 float4 slots, 8 per thread.
#pragma unroll
        for (int it = 0; it < 8; it++) {
            int r = lr + it * 16;                    // q row 0..127
            size_t p = (size_t)(q0 + r) * S + k0 + lc * 4;
            uint2 ue = *(const uint2*)&eb[p];
            __half2 e01 = *(__half2*)&ue.x, e23 = *(__half2*)&ue.y;
            float2 f01 = __half22float2(e01), f23 = __half22float2(e23);
            float rrq = rr[r];
            float a0 = f01.x * rrq, a1 = f01.y * rrq;
            float a2 = f23.x * rrq, a3 = f23.y * rrq;
            *(float4*)&ab[p] = make_float4(a0, a1, a2, a3);  // final attn
            uint2 ua;
            ua.x = cvt2h(a0, a1);
            ua.y = cvt2h(a2, a3);
            *(uint2*)&sA[r * 72 + lc * 4] = ua;
        }
        // V: 64k x 64d fp16, uint4 (8 halves) per access: 512 slots, 2/thread
#pragma unroll
        for (int it = 0; it < 2; it++) {
            int slot = tid + it * 256;
            int r = slot >> 3, c8 = (slot & 7) * 8;
            *(uint4*)&sV[r * 72 + c8] = *(const uint4*)&V16[vb + (size_t)(k0 + r) * HD + c8];
        }
        __syncthreads();
#pragma unroll
        for (int kk = 0; kk < 64; kk += 16) {
            wmma::fragment<wmma::matrix_a, 16, 16, 16, __half, wmma::row_major> af[2];
#pragma unroll
            for (int i = 0; i < 2; i++)
                wmma::load_matrix_sync(af[i], sA + (wm * 32 + i * 16) * 72 + kk, 72);
#pragma unroll
            for (int j = 0; j < 2; j++) {
                wmma::fragment<wmma::matrix_b, 16, 16, 16, __half, wmma::row_major> bv;
                wmma::load_matrix_sync(bv, sV + kk * 72 + wn * 32 + j * 16, 72);
#pragma unroll
                for (int i = 0; i < 2; i++)
                    wmma::mma_sync(acc[i][j], af[i], bv, acc[i][j]);
            }
        }
        __syncthreads();
    }

#pragma unroll
    for (int i = 0; i < 2; i++)
#pragma unroll
        for (int j = 0; j < 2; j++) {
            int m = q0 + wm * 32 + i * 16;
            int n = wn * 32 + j * 16;
            float* p = ctx + ((size_t)b * S + m) * DD + h * HD + n;
            wmma::store_matrix_sync(p, acc[i][j], DD, wmma::mem_row_major);
        }
}

// ---------------------------------------------------------------------------
extern "C" void kernel_launch(void* const* d_in, const int* in_sizes, int n_in,
                              void* d_out, int out_size) {
    const float* query = (const float*)d_in[0];
    const float* key   = (const float*)d_in[1];
    const float* value = (const float*)d_in[2];
    const void*  mask  = d_in[3];
    const float* Wq = (const float*)d_in[4];
    const float* bq = (const float*)d_in[5];
    const float* Wk = (const float*)d_in[6];
    const float* bk = (const float*)d_in[7];
    const float* Wv = (const float*)d_in[8];
    const float* bv = (const float*)d_in[9];

    float* ctx = (float*)d_out;

    __half *q16, *k16, *v16, *e16;
    float *rowsum, *attn_fallback;
    unsigned char* mu8;
    cudaGetSymbolAddress((void**)&q16, g_q16);
    cudaGetSymbolAddress((void**)&k16, g_k16);
    cudaGetSymbolAddress((void**)&v16, g_v16);
    cudaGetSymbolAddress((void**)&e16, g_e16);
    cudaGetSymbolAddress((void**)&mu8, g_mask_u8);
    cudaGetSymbolAddress((void**)&rowsum, g_rowsum);
    cudaGetSymbolAddress((void**)&attn_fallback, g_attn_scratch);

    const long long CTX_ELEMS  = (long long)BB * S * DD;
    const long long ATTN_ELEMS = (long long)BH * S * S;
    float* attn = ((long long)out_size >= CTX_ELEMS + ATTN_ELEMS)
                      ? (ctx + CTX_ELEMS) : attn_fallback;

    const int PROJ_SMEM   = 128 * 136 * 4;          // 69632
    const int SCORES_SMEM = 128 * 136 * 4;          // 69632 (sC dominates)
    cudaFuncSetAttribute(proj_wmma, cudaFuncAttributeMaxDynamicSharedMemorySize, PROJ_SMEM);
    cudaFuncSetAttribute(scores_wmma, cudaFuncAttributeMaxDynamicSharedMemorySize, SCORES_SMEM);

    detect_mask_kernel<<<1, 256>>>((const unsigned int*)mask);
    convert_mask_kernel<<<MASK_N / 256, 256>>>(mask, mu8);
    cudaMemsetAsync(rowsum, 0, BH * S * sizeof(float));

    proj_wmma<<<dim3(DD / 128, MROWS / 128, 3), 256, PROJ_SMEM>>>(
        query, key, value, Wq, Wk, Wv, bq, bk, bv, q16, k16, v16);

    scores_wmma<<<dim3(S / 128, S / 128, BH), 256, SCORES_SMEM>>>(
        q16, k16, mu8, e16, rowsum);

    av_fp16<<<dim3(S / 128, BH), 256>>>(e16, v16, rowsum, attn, ctx);
}